// round 14
// baseline (speedup 1.0000x reference)
#include <cuda_runtime.h>
#include <cuda_bf16.h>
#include <stdint.h>
#include <math.h>

#define B_   2
#define T_   2048
#define BT_  (B_*T_)
#define DM_  1024
#define H_   16
#define DH_  64
#define DC1_ 384
#define DC_  256
#define DR_  32
#define DQK_ 96
#define NSPLIT 4

// ---------------- scratch (device globals: alloc-free) ----------------
__device__ float g_w1[DM_*672];
__device__ float g_w2[DC1_*1536];
__device__ float g_w3[DC_*2048];
__device__ float g_w4[DM_*DM_];
__device__ float g_c1[BT_*672];
__device__ float g_c2[BT_*1536];
__device__ float g_c3[BT_*2048];
__device__ float g_attnS[NSPLIT][BT_*DM_];   // per-split partial O; combined into [0]
__device__ float g_plS[NSPLIT][BT_*H_];      // per-split partial row sums
__device__ __nv_bfloat16 g_qh[BT_*H_*DQK_];
__device__ __nv_bfloat16 g_ql[BT_*H_*DQK_];
__device__ __nv_bfloat16 g_kh[BT_*H_*DQK_];
__device__ __nv_bfloat16 g_kl[BT_*H_*DQK_];
__device__ __nv_bfloat16 g_vth[B_*H_*DH_*T_];
__device__ __nv_bfloat16 g_vtl[B_*H_*DH_*T_];

__device__ __forceinline__ unsigned f2tf(float f) {
    unsigned u; asm("cvt.rna.tf32.f32 %0, %1;" : "=r"(u) : "f"(f)); return u;
}
__device__ __forceinline__ float f2tf_f(float f) {
    unsigned u = f2tf(f); return __uint_as_float(u);
}
__device__ __forceinline__ float4 f2tf_v4(float4 v) {
    v.x = f2tf_f(v.x); v.y = f2tf_f(v.y); v.z = f2tf_f(v.z); v.w = f2tf_f(v.w);
    return v;
}

// ---------------- fused weight packing ----------------
#define N1_ (DM_*672/4)
#define N2_ (DC1_*1536/4)
#define N3_ (DC_*2048/4)
#define N4_ (DM_*DM_/4)

__global__ __launch_bounds__(256) void pack_all(
        const float* __restrict__ wdq, const float* __restrict__ wdkv,
        const float* __restrict__ wrk, const float* __restrict__ wuq,
        const float* __restrict__ wrq, const float* __restrict__ wuk,
        const float* __restrict__ wuv, const float* __restrict__ wo) {
    const int total = N1_ + N2_ + N3_ + N4_;
    for (int i = blockIdx.x * 256 + threadIdx.x; i < total; i += gridDim.x * 256) {
        if (i < N1_) {
            int k = i / 168, n = (i % 168) * 4;
            float4 v;
            if (n < 384)      v = *(const float4*)(wdq  + (size_t)k * 384 + n);
            else if (n < 640) v = *(const float4*)(wdkv + (size_t)k * 256 + (n - 384));
            else              v = *(const float4*)(wrk  + (size_t)k * 32  + (n - 640));
            *(float4*)(g_w1 + (size_t)k * 672 + n) = f2tf_v4(v);
        } else if (i < N1_ + N2_) {
            int j = i - N1_;
            int k = j / 384, n = (j % 384) * 4;
            float4 v = (n < 1024) ? *(const float4*)(wuq + (size_t)k * 1024 + n)
                                  : *(const float4*)(wrq + (size_t)k * 512 + (n - 1024));
            *(float4*)(g_w2 + (size_t)k * 1536 + n) = f2tf_v4(v);
        } else if (i < N1_ + N2_ + N3_) {
            int j = i - N1_ - N2_;
            int k = j / 512, n = (j % 512) * 4;
            float4 v = (n < 1024) ? *(const float4*)(wuk + (size_t)k * 1024 + n)
                                  : *(const float4*)(wuv + (size_t)k * 1024 + (n - 1024));
            *(float4*)(g_w3 + (size_t)k * 2048 + n) = f2tf_v4(v);
        } else {
            int j = i - N1_ - N2_ - N3_;
            float4 v = *(const float4*)(wo + (size_t)j * 4);
            *(float4*)(g_w4 + (size_t)j * 4) = f2tf_v4(v);
        }
    }
}

// ---------------- TF32 GEMM core (B pre-rounded to TF32) ----------------
__device__ __forceinline__ void mma_tf32(float* c, const unsigned* a, const unsigned* b) {
    asm volatile(
        "mma.sync.aligned.m16n8k8.row.col.f32.tf32.tf32.f32 "
        "{%0,%1,%2,%3}, {%4,%5,%6,%7}, {%8,%9}, {%0,%1,%2,%3};"
        : "+f"(c[0]), "+f"(c[1]), "+f"(c[2]), "+f"(c[3])
        : "r"(a[0]), "r"(a[1]), "r"(a[2]), "r"(a[3]), "r"(b[0]), "r"(b[1]));
}

__device__ __forceinline__ void gemm_core(
        const float* __restrict__ A, const float* __restrict__ Bm,
        float* __restrict__ C, int N, int K, int lda, int ldc,
        int m0, int n0) {
    __shared__ float As[2][128][20];
    __shared__ float Bs[2][16][136];

    const int tid  = threadIdx.x;
    const int lane = tid & 31, warp = tid >> 5;
    const int gr = lane >> 2, tg = lane & 3;
    const int wm = (warp >> 2) << 6;
    const int wn = (warp & 3) << 5;

    float acc[4][4][4];
    #pragma unroll
    for (int i = 0; i < 4; i++)
        #pragma unroll
        for (int j = 0; j < 4; j++)
            #pragma unroll
            for (int r = 0; r < 4; r++) acc[i][j][r] = 0.f;

    #define LOAD_STAGE(BUF, K0)                                                       \
    {                                                                                 \
        _Pragma("unroll")                                                             \
        for (int u = 0; u < 2; u++) {                                                 \
            int idx = tid + (u << 8);                                                 \
            int r = idx >> 2, kq = (idx & 3) << 2;                                    \
            unsigned d = (unsigned)__cvta_generic_to_shared(&As[BUF][r][kq]);         \
            const float* s = A + (size_t)(m0 + r) * lda + (K0) + kq;                  \
            asm volatile("cp.async.ca.shared.global [%0], [%1], 16;\n"                \
                         :: "r"(d), "l"(s));                                          \
        }                                                                             \
        _Pragma("unroll")                                                             \
        for (int u = 0; u < 2; u++) {                                                 \
            int idx = tid + (u << 8);                                                 \
            int r = idx >> 5, nq = (idx & 31) << 2;                                   \
            unsigned d = (unsigned)__cvta_generic_to_shared(&Bs[BUF][r][nq]);         \
            const float* s = Bm + (size_t)((K0) + r) * N + n0 + nq;                   \
            int sz = (n0 + nq < N) ? 16 : 0;                                          \
            asm volatile("cp.async.ca.shared.global [%0], [%1], 16, %2;\n"            \
                         :: "r"(d), "l"(s), "r"(sz));                                 \
        }                                                                             \
        asm volatile("cp.async.commit_group;\n");                                     \
    }

    int buf = 0;
    LOAD_STAGE(0, 0);

    for (int k0 = 0; k0 < K; k0 += 16) {
        if (k0 + 16 < K) {
            LOAD_STAGE(buf ^ 1, k0 + 16);
            asm volatile("cp.async.wait_group 1;\n");
        } else {
            asm volatile("cp.async.wait_group 0;\n");
        }
        __syncthreads();

        #pragma unroll
        for (int kk = 0; kk < 16; kk += 8) {
            unsigned af[4][4], bf[4][2];
            #pragma unroll
            for (int mt = 0; mt < 4; mt++) {
                int m = wm + (mt << 4);
                af[mt][0] = f2tf(As[buf][m + gr    ][kk + tg    ]);
                af[mt][1] = f2tf(As[buf][m + gr + 8][kk + tg    ]);
                af[mt][2] = f2tf(As[buf][m + gr    ][kk + tg + 4]);
                af[mt][3] = f2tf(As[buf][m + gr + 8][kk + tg + 4]);
            }
            #pragma unroll
            for (int nt = 0; nt < 4; nt++) {
                int n = wn + (nt << 3);
                bf[nt][0] = __float_as_uint(Bs[buf][kk + tg    ][n + gr]);
                bf[nt][1] = __float_as_uint(Bs[buf][kk + tg + 4][n + gr]);
            }
            #pragma unroll
            for (int mt = 0; mt < 4; mt++)
                #pragma unroll
                for (int nt = 0; nt < 4; nt++)
                    mma_tf32(acc[mt][nt], af[mt], bf[nt]);
        }
        __syncthreads();
        buf ^= 1;
    }
    #undef LOAD_STAGE

    #pragma unroll
    for (int mt = 0; mt < 4; mt++) {
        #pragma unroll
        for (int nt = 0; nt < 4; nt++) {
            int m = m0 + wm + (mt << 4) + gr;
            int n = n0 + wn + (nt << 3) + (tg << 1);
            if (n < N) {
                *(float2*)&C[(size_t)m * ldc + n]       = make_float2(acc[mt][nt][0], acc[mt][nt][1]);
                *(float2*)&C[(size_t)(m + 8) * ldc + n] = make_float2(acc[mt][nt][2], acc[mt][nt][3]);
            }
        }
    }
}

__global__ __launch_bounds__(256) void gemm_tf32(
        const float* __restrict__ A, const float* __restrict__ Bm,
        float* __restrict__ C, int N, int K, int lda, int ldc) {
    gemm_core(A, Bm, C, N, K, lda, ldc, blockIdx.y << 7, blockIdx.x << 7);
}

__global__ __launch_bounds__(256) void gemm_fused23() {
    const int bx = blockIdx.x;
    if (bx < 12) {
        gemm_core(g_c1,       g_w2, g_c2, 1536, DC1_, 672, 1536, blockIdx.y << 7, bx << 7);
    } else {
        gemm_core(g_c1 + 384, g_w3, g_c3, 2048, DC_,  672, 2048, blockIdx.y << 7, (bx - 12) << 7);
    }
}

// ---------------- fused prep: build_qk + convert_v ----------------
#define QK_BLOCKS (BT_ * H_ / 8)          // 8192
#define CV_BLOCKS (T_ / 64 * H_ * B_)     // 1024

__global__ __launch_bounds__(256) void prep_all() {
    __shared__ float vs[64][65];
    const int bx = blockIdx.x;
    if (bx < QK_BLOCKS) {
        const int idx  = bx * 8 + (threadIdx.x >> 5);
        const int lane = threadIdx.x & 31;
        const int bt = idx >> 4, h = idx & 15;
        const int t  = bt & (T_ - 1);

        const float* c2p = g_c2 + (size_t)bt * 1536 + h * DH_;
        const float* c3p = g_c3 + (size_t)bt * 2048 + h * DH_;
        float q0 = c2p[lane], q1 = c2p[lane + 32];
        float k0 = c3p[lane], k1 = c3p[lane + 32];

        const int j = lane & 15;
        float inv = exp2f(-(float)j * 0.8304820237218406f);
        float ang = (float)t * inv;
        float c = cosf(ang), sn = sinf(ang);
        const float* qr = g_c2 + (size_t)bt * 1536 + 1024 + h * DR_;
        const float* kr = g_c1 + (size_t)bt * 672 + 640;
        float x1 = qr[j], x2 = qr[16 + j];
        float y1 = kr[j], y2 = kr[16 + j];
        float q2, k2;
        if (lane < 16) { q2 = x1 * c - x2 * sn;  k2 = y1 * c - y2 * sn; }
        else           { q2 = x1 * sn + x2 * c;  k2 = y1 * sn + y2 * c; }

        float sq = q0 * q0 + q1 * q1 + q2 * q2;
        float sk = k0 * k0 + k1 * k1 + k2 * k2;
        #pragma unroll
        for (int o = 16; o > 0; o >>= 1) {
            sq += __shfl_xor_sync(0xffffffffu, sq, o);
            sk += __shfl_xor_sync(0xffffffffu, sk, o);
        }
        const float scale = 0.10206207261596577f;
        float rq = rsqrtf(sq * (1.f / 96.f) + 1e-6f) * scale;
        float rk = rsqrtf(sk * (1.f / 96.f) + 1e-6f);

        float qs0 = q0 * rq, qs1 = q1 * rq, qs2 = q2 * rq;
        float ks0 = k0 * rk, ks1 = k1 * rk, ks2 = k2 * rk;
        size_t o = (size_t)idx * DQK_;
        __nv_bfloat16 hq0 = __float2bfloat16(qs0), hq1 = __float2bfloat16(qs1), hq2 = __float2bfloat16(qs2);
        __nv_bfloat16 hk0 = __float2bfloat16(ks0), hk1 = __float2bfloat16(ks1), hk2 = __float2bfloat16(ks2);
        g_qh[o + lane]      = hq0; g_ql[o + lane]      = __float2bfloat16(qs0 - __bfloat162float(hq0));
        g_qh[o + lane + 32] = hq1; g_ql[o + lane + 32] = __float2bfloat16(qs1 - __bfloat162float(hq1));
        g_qh[o + lane + 64] = hq2; g_ql[o + lane + 64] = __float2bfloat16(qs2 - __bfloat162float(hq2));
        g_kh[o + lane]      = hk0; g_kl[o + lane]      = __float2bfloat16(ks0 - __bfloat162float(hk0));
        g_kh[o + lane + 32] = hk1; g_kl[o + lane + 32] = __float2bfloat16(ks1 - __bfloat162float(hk1));
        g_kh[o + lane + 64] = hk2; g_kl[o + lane + 64] = __float2bfloat16(ks2 - __bfloat162float(hk2));
    } else {
        const int cb = bx - QK_BLOCKS;
        const int tt = (cb & (T_ / 64 - 1)) * 64;
        const int h  = (cb >> 5) & 15;
        const int b  = cb >> 9;
        const int tid = threadIdx.x;
        for (int i = tid; i < 64 * 16; i += 256) {
            int r = i >> 4, c4 = i & 15;
            float4 v = *(const float4*)(g_c3 + (size_t)(b * T_ + tt + r) * 2048 + 1024 + h * DH_ + (c4 << 2));
            vs[r][c4 * 4 + 0] = v.x; vs[r][c4 * 4 + 1] = v.y;
            vs[r][c4 * 4 + 2] = v.z; vs[r][c4 * 4 + 3] = v.w;
        }
        __syncthreads();
        for (int i = tid; i < 64 * 64; i += 256) {
            int d = i >> 6, t = i & 63;
            float x = vs[t][d];
            __nv_bfloat16 hb = __float2bfloat16(x);
            size_t o = ((size_t)(b * H_ + h) * DH_ + d) * T_ + tt + t;
            g_vth[o] = hb;
            g_vtl[o] = __float2bfloat16(x - __bfloat162float(hb));
        }
    }
}

// ---------------- flash attention v10: 4-way split-KV, additive combine ----------------
__device__ __forceinline__ void mma_bf16(float* c, const unsigned* a, const unsigned* b) {
    asm volatile(
        "mma.sync.aligned.m16n8k16.row.col.f32.bf16.bf16.f32 "
        "{%0,%1,%2,%3}, {%4,%5,%6,%7}, {%8,%9}, {%0,%1,%2,%3};"
        : "+f"(c[0]), "+f"(c[1]), "+f"(c[2]), "+f"(c[3])
        : "r"(a[0]), "r"(a[1]), "r"(a[2]), "r"(a[3]), "r"(b[0]), "r"(b[1]));
}
__device__ __forceinline__ unsigned packbf(float lo, float hi) {
    unsigned r; asm("cvt.rn.bf16x2.f32 %0, %1, %2;" : "=r"(r) : "f"(hi), "f"(lo));
    return r;
}
__device__ __forceinline__ void splitpack(float x0, float x1, unsigned& h, unsigned& l) {
    h = packbf(x0, x1);
    float h0 = __uint_as_float(h << 16);
    float h1 = __uint_as_float(h & 0xffff0000u);
    l = packbf(x0 - h0, x1 - h1);
}
__device__ __forceinline__ void cpa16(void* dst, const void* src) {
    unsigned d = (unsigned)__cvta_generic_to_shared(dst);
    asm volatile("cp.async.ca.shared.global [%0], [%1], 16;\n" :: "r"(d), "l"(src));
}
__device__ __forceinline__ void ldm_x4(unsigned* r, const void* p) {
    unsigned a = (unsigned)__cvta_generic_to_shared(p);
    asm volatile("ldmatrix.sync.aligned.m8n8.x4.shared.b16 {%0,%1,%2,%3}, [%4];"
                 : "=r"(r[0]), "=r"(r[1]), "=r"(r[2]), "=r"(r[3]) : "r"(a));
}

#define QLD 104
#define VLD 136
#define S_KL   (128*QLD)
#define S_VTH  (2*128*QLD)
#define S_VTL  (2*128*QLD + 64*VLD)
#define STG    (2*128*QLD + 2*64*VLD)
#define FL_SMEM (2*STG*2)

__global__ __launch_bounds__(256) void flash10() {
    extern __shared__ __nv_bfloat16 sb[];

    // grid.x = NSPLIT * (T/128): heavy qt first
    const int sx = blockIdx.x;
    const int qt = (gridDim.x / NSPLIT) - 1 - (sx / NSPLIT);
    const int split = sx % NSPLIT;
    const int h  = blockIdx.y;
    const int b  = blockIdx.z;
    const int tid = threadIdx.x, lane = tid & 31, w = tid >> 5;
    const int gr = lane >> 2, tg = lane & 3;
    const int li = lane & 7, lsel = lane >> 3;

    const int nkt   = qt + 1;
    const int chunk = (nkt + NSPLIT - 1) / NSPLIT;
    const int ktlo  = split * chunk;
    const int kthi  = min(nkt, ktlo + chunk);
    const size_t kvbase = (size_t)(b * H_ + h) * DH_ * T_;

    float l_[2] = {0.f, 0.f};
    float O[8][4];
    #pragma unroll
    for (int nt = 0; nt < 8; nt++)
        #pragma unroll
        for (int j = 0; j < 4; j++) O[nt][j] = 0.f;

    const int rowlo = qt * 128 + w * 16;

    if (ktlo < kthi) {
        #define PREFETCH(KT, BUF)                                                          \
        {                                                                                  \
            __nv_bfloat16* st = sb + (BUF) * STG;                                          \
            const __nv_bfloat16* khg = g_kh + ((size_t)(b * T_ + (KT) * 128) * H_ + h) * DQK_; \
            const __nv_bfloat16* klg = g_kl + ((size_t)(b * T_ + (KT) * 128) * H_ + h) * DQK_; \
            for (int i = tid; i < 128 * 12; i += 256) {                                    \
                int r = i / 12, c = i % 12;                                                \
                cpa16(&st[r * QLD + c * 8],        khg + (size_t)r * (H_ * DQK_) + c * 8); \
                cpa16(&st[S_KL + r * QLD + c * 8], klg + (size_t)r * (H_ * DQK_) + c * 8); \
            }                                                                              \
            const __nv_bfloat16* vhg = g_vth + kvbase + (KT) * 128;                        \
            const __nv_bfloat16* vlg = g_vtl + kvbase + (KT) * 128;                        \
            for (int i = tid; i < 64 * 16; i += 256) {                                     \
                int d = i >> 4, c = i & 15;                                                \
                cpa16(&st[S_VTH + d * VLD + c * 8], vhg + (size_t)d * T_ + c * 8);         \
                cpa16(&st[S_VTL + d * VLD + c * 8], vlg + (size_t)d * T_ + c * 8);         \
            }                                                                              \
            asm volatile("cp.async.commit_group;\n");                                     \
        }

        PREFETCH(ktlo, ktlo & 1);

        unsigned qah[6][4], qal[6][4];
        {
            const int r0 = qt * 128 + w * 16 + gr;
            const __nv_bfloat16* qhg = g_qh + ((size_t)(b * T_ + r0) * H_ + h) * DQK_;
            const __nv_bfloat16* qlg = g_ql + ((size_t)(b * T_ + r0) * H_ + h) * DQK_;
            const size_t rs = (size_t)8 * H_ * DQK_;
            #pragma unroll
            for (int ks = 0; ks < 6; ks++) {
                int c = ks * 16 + 2 * tg;
                qah[ks][0] = *(const unsigned*)(qhg + c);
                qah[ks][1] = *(const unsigned*)(qhg + rs + c);
                qah[ks][2] = *(const unsigned*)(qhg + c + 8);
                qah[ks][3] = *(const unsigned*)(qhg + rs + c + 8);
                qal[ks][0] = *(const unsigned*)(qlg + c);
                qal[ks][1] = *(const unsigned*)(qlg + rs + c);
                qal[ks][2] = *(const unsigned*)(qlg + c + 8);
                qal[ks][3] = *(const unsigned*)(qlg + rs + c + 8);
            }
        }

        for (int kt = ktlo; kt < kthi; kt++) {
            asm volatile("cp.async.wait_group 0;\n");
            __syncthreads();

            if (kt + 1 < kthi) PREFETCH(kt + 1, (kt + 1) & 1);

            const __nv_bfloat16* st  = sb + (kt & 1) * STG;
            const __nv_bfloat16* Kh  = st;
            const __nv_bfloat16* Kl  = st + S_KL;
            const __nv_bfloat16* Vth = st + S_VTH;
            const __nv_bfloat16* Vtl = st + S_VTL;

            #pragma unroll
            for (int khalf = 0; khalf < 2; khalf++) {
                const int colbase = kt * 128 + khalf * 64;
                if (colbase > rowlo + 15) break;

                float s[8][4];
                #pragma unroll
                for (int nt = 0; nt < 8; nt++)
                    #pragma unroll
                    for (int j = 0; j < 4; j++) s[nt][j] = 0.f;

                #pragma unroll
                for (int ks = 0; ks < 6; ks++) {
                    #pragma unroll
                    for (int np = 0; np < 4; np++) {
                        unsigned bh[4], bl[4];
                        int r = khalf * 64 + np * 16 + ((lsel >> 1) << 3) + li;
                        int c = ks * 16 + ((lsel & 1) << 3);
                        ldm_x4(bh, &Kh[r * QLD + c]);
                        ldm_x4(bl, &Kl[r * QLD + c]);
                        mma_bf16(s[2*np    ], qah[ks], &bh[0]);
                        mma_bf16(s[2*np    ], qah[ks], &bl[0]);
                        mma_bf16(s[2*np    ], qal[ks], &bh[0]);
                        mma_bf16(s[2*np + 1], qah[ks], &bh[2]);
                        mma_bf16(s[2*np + 1], qah[ks], &bl[2]);
                        mma_bf16(s[2*np + 1], qal[ks], &bh[2]);
                    }
                }

                if (colbase + 63 > rowlo) {
                    const int rowA = rowlo + gr, rowB = rowA + 8;
                    #pragma unroll
                    for (int nt = 0; nt < 8; nt++) {
                        int cb = colbase + nt * 8 + 2 * tg;
                        if (cb     > rowA) s[nt][0] = -1e30f;
                        if (cb + 1 > rowA) s[nt][1] = -1e30f;
                        if (cb     > rowB) s[nt][2] = -1e30f;
                        if (cb + 1 > rowB) s[nt][3] = -1e30f;
                    }
                }

                #pragma unroll
                for (int nt = 0; nt < 8; nt++) {
                    s[nt][0] = __expf(s[nt][0] - 10.f);
                    s[nt][1] = __expf(s[nt][1] - 10.f);
                    s[nt][2] = __expf(s[nt][2] - 10.f);
                    s[nt][3] = __expf(s[nt][3] - 10.f);
                    l_[0] += s[nt][0] + s[nt][1];
                    l_[1] += s[nt][2] + s[nt][3];
                }

                #pragma unroll
                for (int kk = 0; kk < 4; kk++) {
                    unsigned ah[4], al[4];
                    splitpack(s[2*kk    ][0], s[2*kk    ][1], ah[0], al[0]);
                    splitpack(s[2*kk    ][2], s[2*kk    ][3], ah[1], al[1]);
                    splitpack(s[2*kk + 1][0], s[2*kk + 1][1], ah[2], al[2]);
                    splitpack(s[2*kk + 1][2], s[2*kk + 1][3], ah[3], al[3]);
                    #pragma unroll
                    for (int np = 0; np < 4; np++) {
                        unsigned bh[4], bl[4];
                        int r = np * 16 + ((lsel >> 1) << 3) + li;
                        int c = khalf * 64 + kk * 16 + ((lsel & 1) << 3);
                        ldm_x4(bh, &Vth[r * VLD + c]);
                        ldm_x4(bl, &Vtl[r * VLD + c]);
                        mma_bf16(O[2*np    ], ah, &bh[0]);
                        mma_bf16(O[2*np    ], ah, &bl[0]);
                        mma_bf16(O[2*np    ], al, &bh[0]);
                        mma_bf16(O[2*np + 1], ah, &bh[2]);
                        mma_bf16(O[2*np + 1], ah, &bl[2]);
                        mma_bf16(O[2*np + 1], al, &bh[2]);
                    }
                }
            }
        }
        #undef PREFETCH
    }

    // partial-sum epilogue: write UNNORMALIZED O + row sums (zeros if range empty)
    float rA = l_[0], rB = l_[1];
    rA += __shfl_xor_sync(0xffffffffu, rA, 1);
    rA += __shfl_xor_sync(0xffffffffu, rA, 2);
    rB += __shfl_xor_sync(0xffffffffu, rB, 1);
    rB += __shfl_xor_sync(0xffffffffu, rB, 2);

    float* obuf = g_attnS[split];
    float* lbuf = g_plS[split];
    const int rowA = qt * 128 + w * 16 + gr;
    float* ob = obuf + (size_t)(b * T_ + rowA) * DM_ + h * DH_;
    #pragma unroll
    for (int nt = 0; nt < 8; nt++) {
        int col = nt * 8 + 2 * tg;
        *(float2*)&ob[col]                   = make_float2(O[nt][0], O[nt][1]);
        *(float2*)&ob[(size_t)8 * DM_ + col] = make_float2(O[nt][2], O[nt][3]);
    }
    if (tg == 0) {
        lbuf[(size_t)(b * T_ + rowA) * H_ + h]     = rA;
        lbuf[(size_t)(b * T_ + rowA + 8) * H_ + h] = rB;
    }
}

// ---------------- combine: g_attnS[0] = sum(OS) / sum(lS) ----------------
__global__ __launch_bounds__(256) void combine_attn() {
    const int i = blockIdx.x * 256 + threadIdx.x;     // float4 index
    const int bt = i >> 8;                            // DM_/4 = 256
    const int h  = ((i & 255) << 2) >> 6;
    float lsum = 0.f;
    #pragma unroll
    for (int s = 0; s < NSPLIT; s++) lsum += g_plS[s][(size_t)bt * H_ + h];
    float inv = 1.f / lsum;
    float4 a = ((const float4*)g_attnS[0])[i];
    #pragma unroll
    for (int s = 1; s < NSPLIT; s++) {
        float4 p = ((const float4*)g_attnS[s])[i];
        a.x += p.x; a.y += p.y; a.z += p.z; a.w += p.w;
    }
    a.x *= inv; a.y *= inv; a.z *= inv; a.w *= inv;
    ((float4*)g_attnS[0])[i] = a;
}

// ---------------- launch ----------------
extern "C" void kernel_launch(void* const* d_in, const int* in_sizes, int n_in,
                              void* d_out, int out_size) {
    const float* x     = (const float*)d_in[0];
    const float* w_dq  = (const float*)d_in[1];
    const float* w_uq  = (const float*)d_in[2];
    const float* w_rq  = (const float*)d_in[3];
    const float* w_dkv = (const float*)d_in[4];
    const float* w_rk  = (const float*)d_in[5];
    const float* w_uk  = (const float*)d_in[6];
    const float* w_uv  = (const float*)d_in[7];
    const float* w_o   = (const float*)d_in[8];
    float* out = (float*)d_out;

    float *w1, *w4, *c1, *attn;
    cudaGetSymbolAddress((void**)&w1,   g_w1);
    cudaGetSymbolAddress((void**)&w4,   g_w4);
    cudaGetSymbolAddress((void**)&c1,   g_c1);
    cudaGetSymbolAddress((void**)&attn, g_attnS);   // g_attnS[0]

    pack_all<<<512, 256>>>(w_dq, w_dkv, w_rk, w_uq, w_rq, w_uk, w_uv, w_o);

    gemm_tf32<<<dim3(6, 32), 256>>>(x, w1, c1, 672, DM_, DM_, 672);
    gemm_fused23<<<dim3(28, 32), 256>>>();

    prep_all<<<QK_BLOCKS + CV_BLOCKS, 256>>>();

    cudaFuncSetAttribute(flash10, cudaFuncAttributeMaxDynamicSharedMemorySize, FL_SMEM);
    flash10<<<dim3(T_ / 128 * NSPLIT, H_, B_), 256, FL_SMEM>>>();

    combine_attn<<<BT_ * DM_ / 4 / 256, 256>>>();

    gemm_tf32<<<dim3(8, 32), 256>>>(attn, w4, out, DM_, DM_, DM_, DM_);
}

// round 15
// speedup vs baseline: 1.0433x; 1.0433x over previous
#include <cuda_runtime.h>
#include <cuda_bf16.h>
#include <stdint.h>
#include <math.h>

#define B_   2
#define T_   2048
#define BT_  (B_*T_)
#define DM_  1024
#define H_   16
#define DH_  64
#define DC1_ 384
#define DC_  256
#define DR_  32
#define DQK_ 96
#define NSPLIT 2
#define NKT_  (T_/128)     // 16 K-tiles per (b,h)

// flash stage geometry (bf16 elems)
#define QLD 104
#define VLD 136
#define S_KL   (128*QLD)
#define S_VTH  (2*128*QLD)
#define S_VTL  (2*128*QLD + 64*VLD)
#define STG    (2*128*QLD + 2*64*VLD)    // 44032 elems = 88064 B
#define STG_BYTES (STG*2)

// ---------------- scratch (device globals: alloc-free) ----------------
__device__ float g_w1[DM_*672];
__device__ float g_w2[DC1_*1536];
__device__ float g_w3[DC_*2048];
__device__ float g_w4[DM_*DM_];
__device__ float g_c1[BT_*672];
__device__ float g_c2[BT_*1536];
__device__ float g_c3[BT_*2048];
__device__ float g_attnS[NSPLIT][BT_*DM_];
__device__ float g_plS[NSPLIT][BT_*H_];
__device__ __nv_bfloat16 g_qh[BT_*H_*DQK_];
__device__ __nv_bfloat16 g_ql[BT_*H_*DQK_];
// contiguous K/V stage images: [b][h][kt][STG]
__device__ __align__(16) __nv_bfloat16 g_kv[B_*H_*NKT_*STG];

__device__ __forceinline__ unsigned f2tf(float f) {
    unsigned u; asm("cvt.rna.tf32.f32 %0, %1;" : "=r"(u) : "f"(f)); return u;
}
__device__ __forceinline__ float f2tf_f(float f) {
    unsigned u = f2tf(f); return __uint_as_float(u);
}
__device__ __forceinline__ float4 f2tf_v4(float4 v) {
    v.x = f2tf_f(v.x); v.y = f2tf_f(v.y); v.z = f2tf_f(v.z); v.w = f2tf_f(v.w);
    return v;
}

// ---------------- fused weight packing ----------------
#define N1_ (DM_*672/4)
#define N2_ (DC1_*1536/4)
#define N3_ (DC_*2048/4)
#define N4_ (DM_*DM_/4)

__global__ __launch_bounds__(256) void pack_all(
        const float* __restrict__ wdq, const float* __restrict__ wdkv,
        const float* __restrict__ wrk, const float* __restrict__ wuq,
        const float* __restrict__ wrq, const float* __restrict__ wuk,
        const float* __restrict__ wuv, const float* __restrict__ wo) {
    const int total = N1_ + N2_ + N3_ + N4_;
    for (int i = blockIdx.x * 256 + threadIdx.x; i < total; i += gridDim.x * 256) {
        if (i < N1_) {
            int k = i / 168, n = (i % 168) * 4;
            float4 v;
            if (n < 384)      v = *(const float4*)(wdq  + (size_t)k * 384 + n);
            else if (n < 640) v = *(const float4*)(wdkv + (size_t)k * 256 + (n - 384));
            else              v = *(const float4*)(wrk  + (size_t)k * 32  + (n - 640));
            *(float4*)(g_w1 + (size_t)k * 672 + n) = f2tf_v4(v);
        } else if (i < N1_ + N2_) {
            int j = i - N1_;
            int k = j / 384, n = (j % 384) * 4;
            float4 v = (n < 1024) ? *(const float4*)(wuq + (size_t)k * 1024 + n)
                                  : *(const float4*)(wrq + (size_t)k * 512 + (n - 1024));
            *(float4*)(g_w2 + (size_t)k * 1536 + n) = f2tf_v4(v);
        } else if (i < N1_ + N2_ + N3_) {
            int j = i - N1_ - N2_;
            int k = j / 512, n = (j % 512) * 4;
            float4 v = (n < 1024) ? *(const float4*)(wuk + (size_t)k * 1024 + n)
                                  : *(const float4*)(wuv + (size_t)k * 1024 + (n - 1024));
            *(float4*)(g_w3 + (size_t)k * 2048 + n) = f2tf_v4(v);
        } else {
            int j = i - N1_ - N2_ - N3_;
            float4 v = *(const float4*)(wo + (size_t)j * 4);
            *(float4*)(g_w4 + (size_t)j * 4) = f2tf_v4(v);
        }
    }
}

// ---------------- TF32 GEMM core (B pre-rounded to TF32) ----------------
__device__ __forceinline__ void mma_tf32(float* c, const unsigned* a, const unsigned* b) {
    asm volatile(
        "mma.sync.aligned.m16n8k8.row.col.f32.tf32.tf32.f32 "
        "{%0,%1,%2,%3}, {%4,%5,%6,%7}, {%8,%9}, {%0,%1,%2,%3};"
        : "+f"(c[0]), "+f"(c[1]), "+f"(c[2]), "+f"(c[3])
        : "r"(a[0]), "r"(a[1]), "r"(a[2]), "r"(a[3]), "r"(b[0]), "r"(b[1]));
}

__device__ __forceinline__ void gemm_core(
        const float* __restrict__ A, const float* __restrict__ Bm,
        float* __restrict__ C, int N, int K, int lda, int ldc,
        int m0, int n0) {
    __shared__ float As[2][128][20];
    __shared__ float Bs[2][16][136];

    const int tid  = threadIdx.x;
    const int lane = tid & 31, warp = tid >> 5;
    const int gr = lane >> 2, tg = lane & 3;
    const int wm = (warp >> 2) << 6;
    const int wn = (warp & 3) << 5;

    float acc[4][4][4];
    #pragma unroll
    for (int i = 0; i < 4; i++)
        #pragma unroll
        for (int j = 0; j < 4; j++)
            #pragma unroll
            for (int r = 0; r < 4; r++) acc[i][j][r] = 0.f;

    #define LOAD_STAGE(BUF, K0)                                                       \
    {                                                                                 \
        _Pragma("unroll")                                                             \
        for (int u = 0; u < 2; u++) {                                                 \
            int idx = tid + (u << 8);                                                 \
            int r = idx >> 2, kq = (idx & 3) << 2;                                    \
            unsigned d = (unsigned)__cvta_generic_to_shared(&As[BUF][r][kq]);         \
            const float* s = A + (size_t)(m0 + r) * lda + (K0) + kq;                  \
            asm volatile("cp.async.ca.shared.global [%0], [%1], 16;\n"                \
                         :: "r"(d), "l"(s));                                          \
        }                                                                             \
        _Pragma("unroll")                                                             \
        for (int u = 0; u < 2; u++) {                                                 \
            int idx = tid + (u << 8);                                                 \
            int r = idx >> 5, nq = (idx & 31) << 2;                                   \
            unsigned d = (unsigned)__cvta_generic_to_shared(&Bs[BUF][r][nq]);         \
            const float* s = Bm + (size_t)((K0) + r) * N + n0 + nq;                   \
            int sz = (n0 + nq < N) ? 16 : 0;                                          \
            asm volatile("cp.async.ca.shared.global [%0], [%1], 16, %2;\n"            \
                         :: "r"(d), "l"(s), "r"(sz));                                 \
        }                                                                             \
        asm volatile("cp.async.commit_group;\n");                                     \
    }

    int buf = 0;
    LOAD_STAGE(0, 0);

    for (int k0 = 0; k0 < K; k0 += 16) {
        if (k0 + 16 < K) {
            LOAD_STAGE(buf ^ 1, k0 + 16);
            asm volatile("cp.async.wait_group 1;\n");
        } else {
            asm volatile("cp.async.wait_group 0;\n");
        }
        __syncthreads();

        #pragma unroll
        for (int kk = 0; kk < 16; kk += 8) {
            unsigned af[4][4], bf[4][2];
            #pragma unroll
            for (int mt = 0; mt < 4; mt++) {
                int m = wm + (mt << 4);
                af[mt][0] = f2tf(As[buf][m + gr    ][kk + tg    ]);
                af[mt][1] = f2tf(As[buf][m + gr + 8][kk + tg    ]);
                af[mt][2] = f2tf(As[buf][m + gr    ][kk + tg + 4]);
                af[mt][3] = f2tf(As[buf][m + gr + 8][kk + tg + 4]);
            }
            #pragma unroll
            for (int nt = 0; nt < 4; nt++) {
                int n = wn + (nt << 3);
                bf[nt][0] = __float_as_uint(Bs[buf][kk + tg    ][n + gr]);
                bf[nt][1] = __float_as_uint(Bs[buf][kk + tg + 4][n + gr]);
            }
            #pragma unroll
            for (int mt = 0; mt < 4; mt++)
                #pragma unroll
                for (int nt = 0; nt < 4; nt++)
                    mma_tf32(acc[mt][nt], af[mt], bf[nt]);
        }
        __syncthreads();
        buf ^= 1;
    }
    #undef LOAD_STAGE

    #pragma unroll
    for (int mt = 0; mt < 4; mt++) {
        #pragma unroll
        for (int nt = 0; nt < 4; nt++) {
            int m = m0 + wm + (mt << 4) + gr;
            int n = n0 + wn + (nt << 3) + (tg << 1);
            if (n < N) {
                *(float2*)&C[(size_t)m * ldc + n]       = make_float2(acc[mt][nt][0], acc[mt][nt][1]);
                *(float2*)&C[(size_t)(m + 8) * ldc + n] = make_float2(acc[mt][nt][2], acc[mt][nt][3]);
            }
        }
    }
}

__global__ __launch_bounds__(256) void gemm_tf32(
        const float* __restrict__ A, const float* __restrict__ Bm,
        float* __restrict__ C, int N, int K, int lda, int ldc) {
    gemm_core(A, Bm, C, N, K, lda, ldc, blockIdx.y << 7, blockIdx.x << 7);
}

__global__ __launch_bounds__(256) void gemm_fused23() {
    const int bx = blockIdx.x;
    if (bx < 12) {
        gemm_core(g_c1,       g_w2, g_c2, 1536, DC1_, 672, 1536, blockIdx.y << 7, bx << 7);
    } else {
        gemm_core(g_c1 + 384, g_w3, g_c3, 2048, DC_,  672, 2048, blockIdx.y << 7, (bx - 12) << 7);
    }
}

// ---------------- fused prep: build_qk + convert_v -> contiguous stage images ----------------
#define QK_BLOCKS (BT_ * H_ / 8)          // 8192
#define CV_BLOCKS (T_ / 64 * H_ * B_)     // 1024

__global__ __launch_bounds__(256) void prep_all() {
    __shared__ float vs[64][65];
    const int bx = blockIdx.x;
    if (bx < QK_BLOCKS) {
        const int idx  = bx * 8 + (threadIdx.x >> 5);
        const int lane = threadIdx.x & 31;
        const int bt = idx >> 4, h = idx & 15;
        const int b  = bt >> 11;              // bt / T_
        const int t  = bt & (T_ - 1);

        const float* c2p = g_c2 + (size_t)bt * 1536 + h * DH_;
        const float* c3p = g_c3 + (size_t)bt * 2048 + h * DH_;
        float q0 = c2p[lane], q1 = c2p[lane + 32];
        float k0 = c3p[lane], k1 = c3p[lane + 32];

        const int j = lane & 15;
        float inv = exp2f(-(float)j * 0.8304820237218406f);
        float ang = (float)t * inv;
        float c = cosf(ang), sn = sinf(ang);
        const float* qr = g_c2 + (size_t)bt * 1536 + 1024 + h * DR_;
        const float* kr = g_c1 + (size_t)bt * 672 + 640;
        float x1 = qr[j], x2 = qr[16 + j];
        float y1 = kr[j], y2 = kr[16 + j];
        float q2, k2;
        if (lane < 16) { q2 = x1 * c - x2 * sn;  k2 = y1 * c - y2 * sn; }
        else           { q2 = x1 * sn + x2 * c;  k2 = y1 * sn + y2 * c; }

        float sq = q0 * q0 + q1 * q1 + q2 * q2;
        float sk = k0 * k0 + k1 * k1 + k2 * k2;
        #pragma unroll
        for (int o = 16; o > 0; o >>= 1) {
            sq += __shfl_xor_sync(0xffffffffu, sq, o);
            sk += __shfl_xor_sync(0xffffffffu, sk, o);
        }
        const float scale = 0.10206207261596577f;
        float rq = rsqrtf(sq * (1.f / 96.f) + 1e-6f) * scale;
        float rk = rsqrtf(sk * (1.f / 96.f) + 1e-6f);

        float qs0 = q0 * rq, qs1 = q1 * rq, qs2 = q2 * rq;
        float ks0 = k0 * rk, ks1 = k1 * rk, ks2 = k2 * rk;

        // Q: per-row layout (unchanged)
        size_t o = (size_t)idx * DQK_;
        __nv_bfloat16 hq0 = __float2bfloat16(qs0), hq1 = __float2bfloat16(qs1), hq2 = __float2bfloat16(qs2);
        g_qh[o + lane]      = hq0; g_ql[o + lane]      = __float2bfloat16(qs0 - __bfloat162float(hq0));
        g_qh[o + lane + 32] = hq1; g_ql[o + lane + 32] = __float2bfloat16(qs1 - __bfloat162float(hq1));
        g_qh[o + lane + 64] = hq2; g_ql[o + lane + 64] = __float2bfloat16(qs2 - __bfloat162float(hq2));

        // K: into contiguous stage image [b][h][kt][Kh|Kl|...]
        const int kt = t >> 7, r = t & 127;
        __nv_bfloat16* kb = g_kv + ((size_t)((b * H_ + h) * NKT_ + kt)) * STG + (size_t)r * QLD;
        __nv_bfloat16* kl = kb + S_KL;
        __nv_bfloat16 hk0 = __float2bfloat16(ks0), hk1 = __float2bfloat16(ks1), hk2 = __float2bfloat16(ks2);
        kb[lane]      = hk0; kl[lane]      = __float2bfloat16(ks0 - __bfloat162float(hk0));
        kb[lane + 32] = hk1; kl[lane + 32] = __float2bfloat16(ks1 - __bfloat162float(hk1));
        kb[lane + 64] = hk2; kl[lane + 64] = __float2bfloat16(ks2 - __bfloat162float(hk2));
    } else {
        const int cb = bx - QK_BLOCKS;
        const int tt = (cb & (T_ / 64 - 1)) * 64;
        const int h  = (cb >> 5) & 15;
        const int b  = cb >> 9;
        const int tid = threadIdx.x;
        for (int i = tid; i < 64 * 16; i += 256) {
            int r = i >> 4, c4 = i & 15;
            float4 v = *(const float4*)(g_c3 + (size_t)(b * T_ + tt + r) * 2048 + 1024 + h * DH_ + (c4 << 2));
            vs[r][c4 * 4 + 0] = v.x; vs[r][c4 * 4 + 1] = v.y;
            vs[r][c4 * 4 + 2] = v.z; vs[r][c4 * 4 + 3] = v.w;
        }
        __syncthreads();
        const int kt = tt >> 7, coloff = tt & 127;
        __nv_bfloat16* stg = g_kv + ((size_t)((b * H_ + h) * NKT_ + kt)) * STG;
        for (int i = tid; i < 64 * 64; i += 256) {
            int d = i >> 6, t = i & 63;
            float x = vs[t][d];
            __nv_bfloat16 hb = __float2bfloat16(x);
            stg[S_VTH + (size_t)d * VLD + coloff + t] = hb;
            stg[S_VTL + (size_t)d * VLD + coloff + t] = __float2bfloat16(x - __bfloat162float(hb));
        }
    }
}

// ---------------- flash attention v11: bulk-copy stages + mbarrier ----------------
__device__ __forceinline__ void mma_bf16(float* c, const unsigned* a, const unsigned* b) {
    asm volatile(
        "mma.sync.aligned.m16n8k16.row.col.f32.bf16.bf16.f32 "
        "{%0,%1,%2,%3}, {%4,%5,%6,%7}, {%8,%9}, {%0,%1,%2,%3};"
        : "+f"(c[0]), "+f"(c[1]), "+f"(c[2]), "+f"(c[3])
        : "r"(a[0]), "r"(a[1]), "r"(a[2]), "r"(a[3]), "r"(b[0]), "r"(b[1]));
}
__device__ __forceinline__ unsigned packbf(float lo, float hi) {
    unsigned r; asm("cvt.rn.bf16x2.f32 %0, %1, %2;" : "=r"(r) : "f"(hi), "f"(lo));
    return r;
}
__device__ __forceinline__ void splitpack(float x0, float x1, unsigned& h, unsigned& l) {
    h = packbf(x0, x1);
    float h0 = __uint_as_float(h << 16);
    float h1 = __uint_as_float(h & 0xffff0000u);
    l = packbf(x0 - h0, x1 - h1);
}
__device__ __forceinline__ void ldm_x4(unsigned* r, const void* p) {
    unsigned a = (unsigned)__cvta_generic_to_shared(p);
    asm volatile("ldmatrix.sync.aligned.m8n8.x4.shared.b16 {%0,%1,%2,%3}, [%4];"
                 : "=r"(r[0]), "=r"(r[1]), "=r"(r[2]), "=r"(r[3]) : "r"(a));
}
__device__ __forceinline__ void mbar_init(unsigned bar, unsigned cnt) {
    asm volatile("mbarrier.init.shared.b64 [%0], %1;" :: "r"(bar), "r"(cnt) : "memory");
}
__device__ __forceinline__ void mbar_wait(unsigned bar, unsigned phase) {
    asm volatile(
        "{\n\t.reg .pred p;\n\t"
        "WL_%=:\n\t"
        "mbarrier.try_wait.parity.acquire.cta.shared::cta.b64 p, [%0], %1, 0x989680;\n\t"
        "@p bra WD_%=;\n\t"
        "bra WL_%=;\n\t"
        "WD_%=:\n\t}"
        :: "r"(bar), "r"(phase) : "memory");
}
__device__ __forceinline__ void bulk_load(unsigned dst, const void* src, unsigned bytes, unsigned bar) {
    asm volatile("mbarrier.arrive.expect_tx.shared.b64 _, [%0], %1;"
                 :: "r"(bar), "r"(bytes) : "memory");
    asm volatile("cp.async.bulk.shared::cluster.global.mbarrier::complete_tx::bytes "
                 "[%0], [%1], %2, [%3];"
                 :: "r"(dst), "l"(src), "r"(bytes), "r"(bar) : "memory");
}

#define FL_SMEM (2*STG_BYTES + 32)       // 2 stages + mbarriers

__global__ __launch_bounds__(256) void flash11() {
    extern __shared__ __nv_bfloat16 sb[];
    const unsigned sbBase = (unsigned)__cvta_generic_to_shared(sb);
    const unsigned bar0 = sbBase + 2 * STG_BYTES;
    const unsigned bar1 = bar0 + 8;

    const int sx = blockIdx.x;
    const int qt = (gridDim.x >> 1) - 1 - (sx >> 1);   // heavy first
    const int split = sx & 1;
    const int h  = blockIdx.y;
    const int b  = blockIdx.z;
    const int tid = threadIdx.x, lane = tid & 31, w = tid >> 5;
    const int gr = lane >> 2, tg = lane & 3;
    const int li = lane & 7, lsel = lane >> 3;

    const int nkt   = qt + 1;
    const int half0 = (nkt + 1) >> 1;
    const int ktlo  = split ? half0 : 0;
    const int kthi  = split ? nkt   : half0;

    if (tid == 0) { mbar_init(bar0, 1); mbar_init(bar1, 1); }
    __syncthreads();

    const __nv_bfloat16* kvbase = g_kv + (size_t)((b * H_ + h) * NKT_) * STG;

    float l_[2] = {0.f, 0.f};
    float O[8][4];
    #pragma unroll
    for (int nt = 0; nt < 8; nt++)
        #pragma unroll
        for (int j = 0; j < 4; j++) O[nt][j] = 0.f;

    const int rowlo = qt * 128 + w * 16;

    if (ktlo < kthi) {
        if (tid == 0)
            bulk_load(sbBase + (ktlo & 1) * STG_BYTES, kvbase + (size_t)ktlo * STG,
                      STG_BYTES, (ktlo & 1) ? bar1 : bar0);

        // Q fragments -> registers
        unsigned qah[6][4], qal[6][4];
        {
            const int r0 = qt * 128 + w * 16 + gr;
            const __nv_bfloat16* qhg = g_qh + ((size_t)(b * T_ + r0) * H_ + h) * DQK_;
            const __nv_bfloat16* qlg = g_ql + ((size_t)(b * T_ + r0) * H_ + h) * DQK_;
            const size_t rs = (size_t)8 * H_ * DQK_;
            #pragma unroll
            for (int ks = 0; ks < 6; ks++) {
                int c = ks * 16 + 2 * tg;
                qah[ks][0] = *(const unsigned*)(qhg + c);
                qah[ks][1] = *(const unsigned*)(qhg + rs + c);
                qah[ks][2] = *(const unsigned*)(qhg + c + 8);
                qah[ks][3] = *(const unsigned*)(qhg + rs + c + 8);
                qal[ks][0] = *(const unsigned*)(qlg + c);
                qal[ks][1] = *(const unsigned*)(qlg + rs + c);
                qal[ks][2] = *(const unsigned*)(qlg + c + 8);
                qal[ks][3] = *(const unsigned*)(qlg + rs + c + 8);
            }
        }

        int ph0 = 0, ph1 = 0;
        for (int kt = ktlo; kt < kthi; kt++) {
            const int s = kt & 1;
            if (s) { mbar_wait(bar1, ph1); ph1 ^= 1; }
            else   { mbar_wait(bar0, ph0); ph0 ^= 1; }
            __syncthreads();   // all threads done with prior reads of the other stage

            if (tid == 0 && kt + 1 < kthi)
                bulk_load(sbBase + ((kt + 1) & 1) * STG_BYTES, kvbase + (size_t)(kt + 1) * STG,
                          STG_BYTES, ((kt + 1) & 1) ? bar1 : bar0);

            const __nv_bfloat16* st  = sb + s * STG;
            const __nv_bfloat16* Kh  = st;
            const __nv_bfloat16* Kl  = st + S_KL;
            const __nv_bfloat16* Vth = st + S_VTH;
            const __nv_bfloat16* Vtl = st + S_VTL;

            #pragma unroll
            for (int khalf = 0; khalf < 2; khalf++) {
                const int colbase = kt * 128 + khalf * 64;
                if (colbase > rowlo + 15) break;

                float sreg[8][4];
                #pragma unroll
                for (int nt = 0; nt < 8; nt++)
                    #pragma unroll
                    for (int j = 0; j < 4; j++) sreg[nt][j] = 0.f;

                #pragma unroll
                for (int ks = 0; ks < 6; ks++) {
                    #pragma unroll
                    for (int np = 0; np < 4; np++) {
                        unsigned bh[4], bl[4];
                        int r = khalf * 64 + np * 16 + ((lsel >> 1) << 3) + li;
                        int c = ks * 16 + ((lsel & 1) << 3);
                        ldm_x4(bh, &Kh[r * QLD + c]);
                        ldm_x4(bl, &Kl[r * QLD + c]);
                        mma_bf16(sreg[2*np    ], qah[ks], &bh[0]);
                        mma_bf16(sreg[2*np    ], qah[ks], &bl[0]);
                        mma_bf16(sreg[2*np    ], qal[ks], &bh[0]);
                        mma_bf16(sreg[2*np + 1], qah[ks], &bh[2]);
                        mma_bf16(sreg[2*np + 1], qah[ks], &bl[2]);
                        mma_bf16(sreg[2*np + 1], qal[ks], &bh[2]);
                    }
                }

                if (colbase + 63 > rowlo) {
                    const int rowA = rowlo + gr, rowB = rowA + 8;
                    #pragma unroll
                    for (int nt = 0; nt < 8; nt++) {
                        int cb = colbase + nt * 8 + 2 * tg;
                        if (cb     > rowA) sreg[nt][0] = -1e30f;
                        if (cb + 1 > rowA) sreg[nt][1] = -1e30f;
                        if (cb     > rowB) sreg[nt][2] = -1e30f;
                        if (cb + 1 > rowB) sreg[nt][3] = -1e30f;
                    }
                }

                #pragma unroll
                for (int nt = 0; nt < 8; nt++) {
                    sreg[nt][0] = __expf(sreg[nt][0] - 10.f);
                    sreg[nt][1] = __expf(sreg[nt][1] - 10.f);
                    sreg[nt][2] = __expf(sreg[nt][2] - 10.f);
                    sreg[nt][3] = __expf(sreg[nt][3] - 10.f);
                    l_[0] += sreg[nt][0] + sreg[nt][1];
                    l_[1] += sreg[nt][2] + sreg[nt][3];
                }

                #pragma unroll
                for (int kk = 0; kk < 4; kk++) {
                    unsigned ah[4], al[4];
                    splitpack(sreg[2*kk    ][0], sreg[2*kk    ][1], ah[0], al[0]);
                    splitpack(sreg[2*kk    ][2], sreg[2*kk    ][3], ah[1], al[1]);
                    splitpack(sreg[2*kk + 1][0], sreg[2*kk + 1][1], ah[2], al[2]);
                    splitpack(sreg[2*kk + 1][2], sreg[2*kk + 1][3], ah[3], al[3]);
                    #pragma unroll
                    for (int np = 0; np < 4; np++) {
                        unsigned bh[4], bl[4];
                        int r = np * 16 + ((lsel >> 1) << 3) + li;
                        int c = khalf * 64 + kk * 16 + ((lsel & 1) << 3);
                        ldm_x4(bh, &Vth[r * VLD + c]);
                        ldm_x4(bl, &Vtl[r * VLD + c]);
                        mma_bf16(O[2*np    ], ah, &bh[0]);
                        mma_bf16(O[2*np    ], ah, &bl[0]);
                        mma_bf16(O[2*np    ], al, &bh[0]);
                        mma_bf16(O[2*np + 1], ah, &bh[2]);
                        mma_bf16(O[2*np + 1], ah, &bl[2]);
                        mma_bf16(O[2*np + 1], al, &bh[2]);
                    }
                }
            }
        }
    }

    // partial-sum epilogue (zeros if range empty)
    float rA = l_[0], rB = l_[1];
    rA += __shfl_xor_sync(0xffffffffu, rA, 1);
    rA += __shfl_xor_sync(0xffffffffu, rA, 2);
    rB += __shfl_xor_sync(0xffffffffu, rB, 1);
    rB += __shfl_xor_sync(0xffffffffu, rB, 2);

    float* obuf = g_attnS[split];
    float* lbuf = g_plS[split];
    const int rowA = qt * 128 + w * 16 + gr;
    float* ob = obuf + (size_t)(b * T_ + rowA) * DM_ + h * DH_;
    #pragma unroll
    for (int nt = 0; nt < 8; nt++) {
        int col = nt * 8 + 2 * tg;
        *(float2*)&ob[col]                   = make_float2(O[nt][0], O[nt][1]);
        *(float2*)&ob[(size_t)8 * DM_ + col] = make_float2(O[nt][2], O[nt][3]);
    }
    if (tg == 0) {
        lbuf[(size_t)(b * T_ + rowA) * H_ + h]     = rA;
        lbuf[(size_t)(b * T_ + rowA + 8) * H_ + h] = rB;
    }
}

// ---------------- combine ----------------
__global__ __launch_bounds__(256) void combine_attn() {
    const int i = blockIdx.x * 256 + threadIdx.x;
    const int bt = i >> 8;
    const int h  = ((i & 255) << 2) >> 6;
    float lsum = 0.f;
    #pragma unroll
    for (int s = 0; s < NSPLIT; s++) lsum += g_plS[s][(size_t)bt * H_ + h];
    float inv = 1.f / lsum;
    float4 a = ((const float4*)g_attnS[0])[i];
    #pragma unroll
    for (int s = 1; s < NSPLIT; s++) {
        float4 p = ((const float4*)g_attnS[s])[i];
        a.x += p.x; a.y += p.y; a.z += p.z; a.w += p.w;
    }
    a.x *= inv; a.y *= inv; a.z *= inv; a.w *= inv;
    ((float4*)g_attnS[0])[i] = a;
}

// ---------------- launch ----------------
extern "C" void kernel_launch(void* const* d_in, const int* in_sizes, int n_in,
                              void* d_out, int out_size) {
    const float* x     = (const float*)d_in[0];
    const float* w_dq  = (const float*)d_in[1];
    const float* w_uq  = (const float*)d_in[2];
    const float* w_rq  = (const float*)d_in[3];
    const float* w_dkv = (const float*)d_in[4];
    const float* w_rk  = (const float*)d_in[5];
    const float* w_uk  = (const float*)d_in[6];
    const float* w_uv  = (const float*)d_in[7];
    const float* w_o   = (const float*)d_in[8];
    float* out = (float*)d_out;

    float *w1, *w4, *c1, *attn;
    cudaGetSymbolAddress((void**)&w1,   g_w1);
    cudaGetSymbolAddress((void**)&w4,   g_w4);
    cudaGetSymbolAddress((void**)&c1,   g_c1);
    cudaGetSymbolAddress((void**)&attn, g_attnS);

    pack_all<<<512, 256>>>(w_dq, w_dkv, w_rk, w_uq, w_rq, w_uk, w_uv, w_o);

    gemm_tf32<<<dim3(6, 32), 256>>>(x, w1, c1, 672, DM_, DM_, 672);
    gemm_fused23<<<dim3(28, 32), 256>>>();

    prep_all<<<QK_BLOCKS + CV_BLOCKS, 256>>>();

    cudaFuncSetAttribute(flash11, cudaFuncAttributeMaxDynamicSharedMemorySize, FL_SMEM);
    flash11<<<dim3(T_ / 128 * NSPLIT, H_, B_), 256, FL_SMEM>>>();

    combine_attn<<<BT_ * DM_ / 4 / 256, 256>>>();

    gemm_tf32<<<dim3(8, 32), 256>>>(attn, w4, out, DM_, DM_, DM_, DM_);
}